// round 2
// baseline (speedup 1.0000x reference)
#include <cuda_runtime.h>
#include <cstdint>
#include <cstddef>

// FPS: B=8, N=131072, NPOINT=1024 -> out [8,1024,3] fp32.
// 8 clusters (one per batch) x 16 CTAs x 256 threads.
// Points live in REGISTERS (f32x2-packed), mindist in registers.
// Per step: packed-f32x2 distance update, REDUX two-phase argmax
// (max dist, tie -> smallest index), DSMEM slot exchange with
// mbarrier release/acquire (no barrier.cluster, no L1 flush).

#define NB      8
#define NPTS    131072
#define NSAMP   1024
#define CSIZE   16
#define TPB     256
#define PPB     (NPTS / CSIZE)        // 8192 points per CTA
#define NPAIRS  (PPB / 2 / TPB)       // 16 point-pairs per thread
#define NPT     (2 * NPAIRS)          // 32 points per thread
#define NWARPS  (TPB / 32)            // 8

struct Smem {
    unsigned long long mbar[2];            // double-buffered arrival barriers
    unsigned long long slots[2][CSIZE];    // per-CTA partials (val<<32 | idx)
    unsigned long long warpred[NWARPS];
    float cent[4];
};

// ---------- asm helpers ----------
__device__ __forceinline__ unsigned ctarank() {
    unsigned r; asm("mov.u32 %0, %%cluster_ctarank;" : "=r"(r)); return r;
}
__device__ __forceinline__ unsigned cvta_s(const void* p) {
    unsigned r;
    asm("{ .reg .u64 t; cvta.to.shared.u64 t, %1; cvt.u32.u64 %0, t; }"
        : "=r"(r) : "l"(p));
    return r;
}
__device__ __forceinline__ unsigned mapa_s(unsigned laddr, unsigned rank) {
    unsigned r;
    asm("mapa.shared::cluster.u32 %0, %1, %2;" : "=r"(r) : "r"(laddr), "r"(rank));
    return r;
}
__device__ __forceinline__ unsigned long long packf2(float lo, float hi) {
    unsigned long long r;
    asm("mov.b64 %0, {%1, %2};" : "=l"(r) : "f"(lo), "f"(hi));
    return r;
}
__device__ __forceinline__ void unpackf2(unsigned long long v, float& lo, float& hi) {
    asm("mov.b64 {%0, %1}, %2;" : "=f"(lo), "=f"(hi) : "l"(v));
}
__device__ __forceinline__ unsigned long long addx2(unsigned long long a,
                                                    unsigned long long b) {
    unsigned long long r;
    asm("add.rn.f32x2 %0, %1, %2;" : "=l"(r) : "l"(a), "l"(b));
    return r;
}
__device__ __forceinline__ unsigned long long mulx2(unsigned long long a,
                                                    unsigned long long b) {
    unsigned long long r;
    asm("mul.rn.f32x2 %0, %1, %2;" : "=l"(r) : "l"(a), "l"(b));
    return r;
}
__device__ __forceinline__ unsigned long long fmx2(unsigned long long a,
                                                   unsigned long long b,
                                                   unsigned long long c) {
    unsigned long long r;
    asm("fma.rn.f32x2 %0, %1, %2, %3;" : "=l"(r) : "l"(a), "l"(b), "l"(c));
    return r;
}
__device__ __forceinline__ void mbar_init(unsigned addr, unsigned cnt) {
    asm volatile("mbarrier.init.shared.b64 [%0], %1;" :: "r"(addr), "r"(cnt) : "memory");
}
__device__ __forceinline__ void st_cluster_u64(unsigned raddr, unsigned long long v) {
    asm volatile("st.shared::cluster.u64 [%0], %1;" :: "r"(raddr), "l"(v) : "memory");
}
__device__ __forceinline__ void mbar_arrive_rel_cluster(unsigned raddr) {
    asm volatile("mbarrier.arrive.release.cluster.shared::cluster.b64 _, [%0];"
                 :: "r"(raddr) : "memory");
}
__device__ __forceinline__ void mbar_wait_acq_cluster(unsigned addr, unsigned ph) {
    asm volatile(
        "{\n\t"
        ".reg .pred P;\n\t"
        "WL%=:\n\t"
        "mbarrier.try_wait.parity.acquire.cluster.shared::cta.b64 P, [%0], %1, 0x989680;\n\t"
        "@P bra WD%=;\n\t"
        "bra WL%=;\n\t"
        "WD%=:\n\t"
        "}"
        :: "r"(addr), "r"(ph) : "memory");
}
__device__ __forceinline__ void cluster_sync_() {
    asm volatile("barrier.cluster.arrive.aligned;" ::: "memory");
    asm volatile("barrier.cluster.wait.aligned;"   ::: "memory");
}

__global__ void __launch_bounds__(TPB, 1)
fps_kernel(const float* __restrict__ xyz, float* __restrict__ out) {
    __shared__ Smem s;

    const int      tid  = threadIdx.x;
    const unsigned lane = tid & 31;
    const unsigned warp = (unsigned)tid >> 5;
    const unsigned rank = ctarank();
    const int      batch = blockIdx.x / CSIZE;

    const float* __restrict__ base = xyz + (size_t)batch * NPTS * 3;
    const unsigned pbase = rank * PPB;

    if (tid == 0) { mbar_init(cvta_s(&s.mbar[0]), CSIZE); mbar_init(cvta_s(&s.mbar[1]), CSIZE); }

    // ---- load this CTA's points into registers, f32x2-packed per pair ----
    // pair j of this thread = global pair (j*TPB + tid); points 2p (lo) and 2p+1 (hi)
    unsigned long long X[NPAIRS], Y[NPAIRS], Z[NPAIRS];
#pragma unroll
    for (int j = 0; j < NPAIRS; ++j) {
        unsigned pi = pbase + 2u * (unsigned)(j * TPB + tid);
        const float2* p = reinterpret_cast<const float2*>(base + (size_t)pi * 3);
        float2 a = p[0];  // x0 y0
        float2 b = p[1];  // z0 x1
        float2 c = p[2];  // y1 z1
        X[j] = packf2(a.x, b.y);
        Y[j] = packf2(a.y, c.x);
        Z[j] = packf2(b.x, c.y);
    }

    float m[NPT];
#pragma unroll
    for (int k = 0; k < NPT; ++k) m[k] = __int_as_float(0x7f800000);  // +inf

    // precompute remote slot/mbar addresses for pushes (warp0 lanes < CSIZE)
    unsigned rs0 = 0, rs1 = 0, rb0 = 0, rb1 = 0;
    if (warp == 0 && lane < CSIZE) {
        rs0 = mapa_s(cvta_s(&s.slots[0][rank]), lane);
        rs1 = mapa_s(cvta_s(&s.slots[1][rank]), lane);
        rb0 = mapa_s(cvta_s(&s.mbar[0]), lane);
        rb1 = mapa_s(cvta_s(&s.mbar[1]), lane);
    }
    const unsigned lb0 = cvta_s(&s.mbar[0]);
    const unsigned lb1 = cvta_s(&s.mbar[1]);

    if (tid == 0) {
        float cx = base[0], cy = base[1], cz = base[2];
        s.cent[0] = cx; s.cent[1] = cy; s.cent[2] = cz;
        if (rank == 0) {
            float* o = out + (size_t)batch * NSAMP * 3;
            o[0] = cx; o[1] = cy; o[2] = cz;
        }
    }
    __syncthreads();
    cluster_sync_();   // mbarrier init visible cluster-wide before first arrive

    unsigned ph0 = 0, ph1 = 0;

    for (int t = 1; t < NSAMP; ++t) {
        const float cx = s.cent[0];
        const float cy = s.cent[1];
        const float cz = s.cent[2];
        const unsigned long long ncx = packf2(-cx, -cx);
        const unsigned long long ncy = packf2(-cy, -cy);
        const unsigned long long ncz = packf2(-cz, -cz);

        float bestv = -1.0f;
        int   bestj = 0;
#pragma unroll
        for (int j = 0; j < NPAIRS; ++j) {
            unsigned long long dx = addx2(X[j], ncx);
            unsigned long long dy = addx2(Y[j], ncy);
            unsigned long long dz = addx2(Z[j], ncz);
            unsigned long long dd = mulx2(dx, dx);
            dd = fmx2(dy, dy, dd);
            dd = fmx2(dz, dz, dd);
            float d0, d1;
            unpackf2(dd, d0, d1);
            float m0 = fminf(m[2 * j],     d0);
            float m1 = fminf(m[2 * j + 1], d1);
            m[2 * j]     = m0;
            m[2 * j + 1] = m1;
            float pm = fmaxf(m0, m1);
            bool  p  = pm > bestv;          // strict > keeps earliest j (smaller idx)
            bestv = fmaxf(bestv, pm);
            bestj = p ? j : bestj;
        }
        // resolve which half of the winning pair (tie -> even = smaller index)
        int half = (m[2 * bestj] == bestv) ? 0 : 1;
        unsigned gidx = pbase + 2u * (unsigned)(bestj * TPB + tid) + (unsigned)half;

        // ---- warp reduce: max dist bits, then min index among maxima ----
        unsigned vb = __float_as_uint(bestv);                 // dist >= 0: int order == float order
        unsigned wv = __reduce_max_sync(0xffffffffu, vb);
        unsigned wc = (vb == wv) ? gidx : 0xffffffffu;
        unsigned wi = __reduce_min_sync(0xffffffffu, wc);
        if (lane == 0) s.warpred[warp] = ((unsigned long long)wv << 32) | wi;
        __syncthreads();

        if (warp == 0) {
            // ---- block reduce over 8 warp partials ----
            unsigned long long wr = (lane < NWARPS) ? s.warpred[lane]
                                                    : 0x00000000ffffffffULL;
            unsigned v = (unsigned)(wr >> 32), i = (unsigned)wr;
            unsigned bv = __reduce_max_sync(0xffffffffu, v);
            unsigned bc = (v == bv) ? i : 0xffffffffu;
            unsigned bi = __reduce_min_sync(0xffffffffu, bc);

            const int par = t & 1;
            if (lane < CSIZE) {
                unsigned long long payload = ((unsigned long long)bv << 32) | bi;
                st_cluster_u64(par ? rs1 : rs0, payload);
                mbar_arrive_rel_cluster(par ? rb1 : rb0);
            }
            // wait for all 16 CTAs' partials
            mbar_wait_acq_cluster(par ? lb1 : lb0, par ? ph1 : ph0);
            if (par) ph1 ^= 1; else ph0 ^= 1;

            // ---- cluster reduce over 16 slots ----
            unsigned long long sl = (lane < CSIZE) ? s.slots[par][lane]
                                                   : 0x00000000ffffffffULL;
            unsigned sv = (unsigned)(sl >> 32), si = (unsigned)sl;
            unsigned cv = __reduce_max_sync(0xffffffffu, sv);
            unsigned cc = (sv == cv) ? si : 0xffffffffu;
            unsigned ci = __reduce_min_sync(0xffffffffu, cc);

            if (lane == 0) {
                const float* p = base + (size_t)ci * 3;   // L2-resident
                float nx = __ldg(p + 0);
                float ny = __ldg(p + 1);
                float nz = __ldg(p + 2);
                s.cent[0] = nx; s.cent[1] = ny; s.cent[2] = nz;
                if (rank == 0) {
                    float* o = out + ((size_t)batch * NSAMP + (size_t)t) * 3;
                    o[0] = nx; o[1] = ny; o[2] = nz;
                }
            }
        }
        __syncthreads();
    }

    // keep CTAs alive until all in-flight DSMEM traffic has landed
    cluster_sync_();
}

extern "C" void kernel_launch(void* const* d_in, const int* in_sizes, int n_in,
                              void* d_out, int out_size) {
    (void)in_sizes; (void)n_in; (void)out_size;
    const float* xyz = (const float*)d_in[0];
    float* out = (float*)d_out;

    cudaFuncSetAttribute(fps_kernel,
                         cudaFuncAttributeNonPortableClusterSizeAllowed, 1);

    cudaLaunchConfig_t cfg = {};
    cfg.gridDim  = dim3(NB * CSIZE, 1, 1);   // 128 CTAs
    cfg.blockDim = dim3(TPB, 1, 1);
    cfg.dynamicSmemBytes = 0;
    cfg.stream = 0;

    cudaLaunchAttribute attr[1];
    attr[0].id = cudaLaunchAttributeClusterDimension;
    attr[0].val.clusterDim.x = CSIZE;
    attr[0].val.clusterDim.y = 1;
    attr[0].val.clusterDim.z = 1;
    cfg.attrs = attr;
    cfg.numAttrs = 1;

    cudaLaunchKernelEx(&cfg, fps_kernel, xyz, out);
}

// round 3
// speedup vs baseline: 1.8364x; 1.8364x over previous
#include <cuda_runtime.h>
#include <cstdint>
#include <cstddef>

// FPS: B=8, N=131072, NPOINT=1024 -> out [8,1024,3] fp32.
// 8 clusters (one per batch) x 8 CTAs x 512 threads.
// Per thread: 32 points = 16 f32x2 pairs; pairs 0..7 live in REGISTERS,
// pairs 8..15 stream from SMEM (all pairs also stored in SMEM for the
// once-per-step candidate coordinate fetch). Argmax = (max dist, min index),
// carried as {bits,idx,x,y,z} through warp REDUX -> block -> DSMEM slots;
// every warp reduces the slots after barrier.cluster, so the next centroid
// lands directly in registers (no L2 fetch, no extra __syncthreads).

#define NB       8
#define NPTS     131072
#define NSAMP    1024
#define CSIZE    8
#define TPB      512
#define PPB      (NPTS / CSIZE)    // 16384 points per CTA
#define PAIRS    (PPB / 2)         // 8192 pairs per CTA
#define REGJ     8                 // pairs/thread in registers
#define TOTJ     16                // pairs/thread total
#define NPT      32                // points/thread
#define NWARPS   (TPB / 32)        // 16

struct __align__(16) Red { unsigned v, i; float x, y, z; unsigned pad[3]; };  // 32B

struct Smem {
    Red warpred[NWARPS];
    Red slots[2][CSIZE];
    unsigned long long xs2[PAIRS];   // packed {x_even, x_odd} per pair
    unsigned long long ys2[PAIRS];
    unsigned long long zs2[PAIRS];
};

// ---------- asm helpers ----------
__device__ __forceinline__ unsigned ctarank() {
    unsigned r; asm("mov.u32 %0, %%cluster_ctarank;" : "=r"(r)); return r;
}
__device__ __forceinline__ unsigned cvta_s(const void* p) {
    unsigned r;
    asm("{ .reg .u64 t; cvta.to.shared.u64 t, %1; cvt.u32.u64 %0, t; }"
        : "=r"(r) : "l"(p));
    return r;
}
__device__ __forceinline__ unsigned mapa_s(unsigned laddr, unsigned rank) {
    unsigned r;
    asm("mapa.shared::cluster.u32 %0, %1, %2;" : "=r"(r) : "r"(laddr), "r"(rank));
    return r;
}
__device__ __forceinline__ unsigned long long packf2(float lo, float hi) {
    unsigned long long r;
    asm("mov.b64 %0, {%1, %2};" : "=l"(r) : "f"(lo), "f"(hi));
    return r;
}
__device__ __forceinline__ void unpackf2(unsigned long long v, float& lo, float& hi) {
    asm("mov.b64 {%0, %1}, %2;" : "=f"(lo), "=f"(hi) : "l"(v));
}
__device__ __forceinline__ unsigned long long addx2(unsigned long long a,
                                                    unsigned long long b) {
    unsigned long long r;
    asm("add.rn.f32x2 %0, %1, %2;" : "=l"(r) : "l"(a), "l"(b));
    return r;
}
__device__ __forceinline__ unsigned long long mulx2(unsigned long long a,
                                                    unsigned long long b) {
    unsigned long long r;
    asm("mul.rn.f32x2 %0, %1, %2;" : "=l"(r) : "l"(a), "l"(b));
    return r;
}
__device__ __forceinline__ unsigned long long fmx2(unsigned long long a,
                                                   unsigned long long b,
                                                   unsigned long long c) {
    unsigned long long r;
    asm("fma.rn.f32x2 %0, %1, %2, %3;" : "=l"(r) : "l"(a), "l"(b), "l"(c));
    return r;
}
__device__ __forceinline__ void st_cluster_v4(unsigned raddr, unsigned a, unsigned b,
                                              unsigned c, unsigned d) {
    asm volatile("st.shared::cluster.v4.b32 [%0], {%1,%2,%3,%4};"
                 :: "r"(raddr), "r"(a), "r"(b), "r"(c), "r"(d) : "memory");
}
__device__ __forceinline__ void st_cluster_u32(unsigned raddr, unsigned v) {
    asm volatile("st.shared::cluster.u32 [%0], %1;" :: "r"(raddr), "r"(v) : "memory");
}
__device__ __forceinline__ void cluster_bar() {
    asm volatile("barrier.cluster.arrive.aligned;" ::: "memory");
    asm volatile("barrier.cluster.wait.aligned;"   ::: "memory");
}

__global__ void __launch_bounds__(TPB, 1)
fps_kernel(const float* __restrict__ xyz, float* __restrict__ out) {
    extern __shared__ __align__(16) unsigned char smem_raw[];
    Smem* s = reinterpret_cast<Smem*>(smem_raw);

    const int      tid  = threadIdx.x;
    const unsigned lane = tid & 31;
    const unsigned warp = (unsigned)tid >> 5;
    const unsigned rank = ctarank();
    const int      batch = blockIdx.x / CSIZE;

    const float* __restrict__ base = xyz + (size_t)batch * NPTS * 3;
    const unsigned pbase = rank * PPB;

    // ---- fill SMEM with ALL pairs (packed), plus register half ----
    for (unsigned P = (unsigned)tid; P < PAIRS; P += TPB) {
        const float2* p = reinterpret_cast<const float2*>(
            base + (size_t)(pbase + 2u * P) * 3);
        float2 a = p[0];  // x0 y0
        float2 b = p[1];  // z0 x1
        float2 c = p[2];  // y1 z1
        s->xs2[P] = packf2(a.x, b.y);
        s->ys2[P] = packf2(a.y, c.x);
        s->zs2[P] = packf2(b.x, c.y);
    }

    unsigned long long X[REGJ], Y[REGJ], Z[REGJ];
#pragma unroll
    for (int j = 0; j < REGJ; ++j) {
        unsigned P = (unsigned)j * TPB + (unsigned)tid;
        const float2* p = reinterpret_cast<const float2*>(
            base + (size_t)(pbase + 2u * P) * 3);
        float2 a = p[0]; float2 b = p[1]; float2 c = p[2];
        X[j] = packf2(a.x, b.y);
        Y[j] = packf2(a.y, c.x);
        Z[j] = packf2(b.x, c.y);
    }

    float m[NPT];
#pragma unroll
    for (int k = 0; k < NPT; ++k) m[k] = __int_as_float(0x7f800000);  // +inf

    // remote slot addresses for pushes (warp0 lanes < CSIZE), both parities
    unsigned rs0 = 0, rs1 = 0;
    if (warp == 0 && lane < CSIZE) {
        rs0 = mapa_s(cvta_s(&s->slots[0][rank]), lane);
        rs1 = mapa_s(cvta_s(&s->slots[1][rank]), lane);
    }

    // initial centroid = point 0 of this batch (broadcast L2 load, once)
    float cx = __ldg(base + 0);
    float cy = __ldg(base + 1);
    float cz = __ldg(base + 2);
    if (rank == 0 && tid == 0) {
        float* o = out + (size_t)batch * NSAMP * 3;
        o[0] = cx; o[1] = cy; o[2] = cz;
    }
    __syncthreads();   // smem points ready

    for (int t = 1; t < NSAMP; ++t) {
        const unsigned long long ncx = packf2(-cx, -cx);
        const unsigned long long ncy = packf2(-cy, -cy);
        const unsigned long long ncz = packf2(-cz, -cz);

        // ---- update mindist; track only the max value ----
        float bm = -1.0f;
#pragma unroll
        for (int j = 0; j < REGJ; ++j) {
            unsigned long long dx = addx2(X[j], ncx);
            unsigned long long dy = addx2(Y[j], ncy);
            unsigned long long dz = addx2(Z[j], ncz);
            unsigned long long dd = mulx2(dx, dx);
            dd = fmx2(dy, dy, dd);
            dd = fmx2(dz, dz, dd);
            float d0, d1; unpackf2(dd, d0, d1);
            float m0 = fminf(m[2 * j], d0);
            float m1 = fminf(m[2 * j + 1], d1);
            m[2 * j] = m0; m[2 * j + 1] = m1;
            bm = fmaxf(bm, fmaxf(m0, m1));
        }
#pragma unroll
        for (int j = REGJ; j < TOTJ; ++j) {
            unsigned P = (unsigned)j * TPB + (unsigned)tid;
            unsigned long long dx = addx2(s->xs2[P], ncx);
            unsigned long long dy = addx2(s->ys2[P], ncy);
            unsigned long long dz = addx2(s->zs2[P], ncz);
            unsigned long long dd = mulx2(dx, dx);
            dd = fmx2(dy, dy, dd);
            dd = fmx2(dz, dz, dd);
            float d0, d1; unpackf2(dd, d0, d1);
            float m0 = fminf(m[2 * j], d0);
            float m1 = fminf(m[2 * j + 1], d1);
            m[2 * j] = m0; m[2 * j + 1] = m1;
            bm = fmaxf(bm, fmaxf(m0, m1));
        }

        // ---- resolve smallest k with m[k]==bm (downward scan) ----
        int kk = 0;
#pragma unroll
        for (int k = NPT - 1; k >= 0; --k)
            if (m[k] == bm) kk = k;

        unsigned Pw   = (unsigned)(kk >> 1) * TPB + (unsigned)tid;
        unsigned gidx = pbase + 2u * Pw + (unsigned)(kk & 1);
        float a0, a1, b0, b1, c0, c1;
        unpackf2(s->xs2[Pw], a0, a1);
        unpackf2(s->ys2[Pw], b0, b1);
        unpackf2(s->zs2[Pw], c0, c1);
        float candx = (kk & 1) ? a1 : a0;
        float candy = (kk & 1) ? b1 : b0;
        float candz = (kk & 1) ? c1 : c0;

        // ---- warp reduce: max dist bits, then min index among maxima ----
        unsigned vb = __float_as_uint(bm);            // d>=0: int order == float order
        unsigned wv = __reduce_max_sync(0xffffffffu, vb);
        unsigned cd = (vb == wv) ? gidx : 0xffffffffu;
        unsigned wi = __reduce_min_sync(0xffffffffu, cd);
        if (cd == wi) {                               // unique winner lane stores
            *reinterpret_cast<uint4*>(&s->warpred[warp]) =
                make_uint4(wv, wi, __float_as_uint(candx), __float_as_uint(candy));
            s->warpred[warp].z = candz;
        }
        __syncthreads();

        const int par = t & 1;

        // ---- block reduce over 16 warp partials + push to all 8 peers ----
        if (warp == 0) {
            unsigned v = 0, i = 0xffffffffu, xb = 0, yb = 0, zb = 0;
            if (lane < NWARPS) {
                uint4 w = *reinterpret_cast<const uint4*>(&s->warpred[lane]);
                v = w.x; i = w.y; xb = w.z; yb = w.w;
                zb = __float_as_uint(s->warpred[lane].z);
            }
            unsigned bv = __reduce_max_sync(0xffffffffu, v);
            unsigned bc = (v == bv) ? i : 0xffffffffu;
            unsigned bi = __reduce_min_sync(0xffffffffu, bc);
            unsigned msk = __ballot_sync(0xffffffffu, bc == bi);
            int L = __ffs(msk) - 1;
            xb = __shfl_sync(0xffffffffu, xb, L);
            yb = __shfl_sync(0xffffffffu, yb, L);
            zb = __shfl_sync(0xffffffffu, zb, L);
            if (lane < CSIZE) {
                unsigned ra = par ? rs1 : rs0;
                st_cluster_v4(ra, bv, bi, xb, yb);
                st_cluster_u32(ra + 16, zb);
            }
        }

        // one cluster barrier per step (arrive releases the DSMEM stores)
        cluster_bar();

        // ---- EVERY warp reduces the 8 slots -> next centroid in registers ----
        {
            unsigned v = 0, i = 0xffffffffu, xb = 0, yb = 0, zb = 0;
            if (lane < CSIZE) {
                uint4 w = *reinterpret_cast<const uint4*>(&s->slots[par][lane]);
                v = w.x; i = w.y; xb = w.z; yb = w.w;
                zb = __float_as_uint(s->slots[par][lane].z);
            }
            unsigned cv = __reduce_max_sync(0xffffffffu, v);
            unsigned cc = (v == cv) ? i : 0xffffffffu;
            unsigned ci = __reduce_min_sync(0xffffffffu, cc);
            unsigned msk = __ballot_sync(0xffffffffu, cc == ci);
            int W = __ffs(msk) - 1;
            cx = __uint_as_float(__shfl_sync(0xffffffffu, xb, W));
            cy = __uint_as_float(__shfl_sync(0xffffffffu, yb, W));
            cz = __uint_as_float(__shfl_sync(0xffffffffu, zb, W));
            if (rank == 0 && tid == 0) {
                float* o = out + ((size_t)batch * NSAMP + (size_t)t) * 3;
                o[0] = cx; o[1] = cy; o[2] = cz;
            }
        }
        // no __syncthreads needed: warpred is re-written only after the next
        // warp-stage, which every warp reaches independently; slots are
        // double-buffered and protected by the cluster barrier.
    }

    cluster_bar();  // keep CTAs alive until all DSMEM traffic has landed
}

extern "C" void kernel_launch(void* const* d_in, const int* in_sizes, int n_in,
                              void* d_out, int out_size) {
    (void)in_sizes; (void)n_in; (void)out_size;
    const float* xyz = (const float*)d_in[0];
    float* out = (float*)d_out;

    cudaFuncSetAttribute(fps_kernel,
                         cudaFuncAttributeMaxDynamicSharedMemorySize,
                         (int)sizeof(Smem));

    cudaLaunchConfig_t cfg = {};
    cfg.gridDim  = dim3(NB * CSIZE, 1, 1);   // 64 CTAs
    cfg.blockDim = dim3(TPB, 1, 1);
    cfg.dynamicSmemBytes = sizeof(Smem);
    cfg.stream = 0;

    cudaLaunchAttribute attr[1];
    attr[0].id = cudaLaunchAttributeClusterDimension;
    attr[0].val.clusterDim.x = CSIZE;
    attr[0].val.clusterDim.y = 1;
    attr[0].val.clusterDim.z = 1;
    cfg.attrs = attr;
    cfg.numAttrs = 1;

    cudaLaunchKernelEx(&cfg, fps_kernel, xyz, out);
}